// round 15
// baseline (speedup 1.0000x reference)
#include <cuda_runtime.h>
#include <cuda_fp16.h>
#include <math.h>
#include <stdint.h>

// ---------------------------------------------------------------------------
// B=2, S=4096, D=1024, H=4096, M=B*S=8192
// ---------------------------------------------------------------------------
#define BB   2
#define SS   4096
#define DD   1024
#define HH   4096
#define MM   (BB * SS)

// ---------------------------------------------------------------------------
// Scratch (static device globals; no runtime allocation allowed)
// ---------------------------------------------------------------------------
__device__ __half g_xh   [MM * DD];
__device__ __half g_wqkvT[3 * DD * DD];
__device__ float  g_bqkv [3 * DD];
__device__ __half g_w1T  [(long long)HH * DD];
__device__ __half g_w2T  [(long long)DD * HH];
__device__ __half g_qkv  [(long long)MM * 3 * DD];
__device__ __half g_at   [(long long)BB * SS * SS];   // exp(logits/32), half
__device__ float  g_rs   [MM];                        // rowsum of exp (atomic)
__device__ float  g_ao   [MM * DD];                   // x + attn_out (fused)
__device__ float  g_x1f  [MM * DD];
__device__ __half g_x1h  [MM * DD];
__device__ __half g_hh   [(long long)MM * HH];
__device__ float  g_ff   [MM * DD];                   // x1 + ffn_out (fused)

// ---------------------------------------------------------------------------
// PTX helpers
// ---------------------------------------------------------------------------
__device__ __forceinline__ void mma_f16(float* c, const uint32_t* a, const uint32_t* b) {
    asm volatile(
        "mma.sync.aligned.m16n8k16.row.col.f32.f16.f16.f32 "
        "{%0,%1,%2,%3}, {%4,%5,%6,%7}, {%8,%9}, {%0,%1,%2,%3};\n"
        : "+f"(c[0]), "+f"(c[1]), "+f"(c[2]), "+f"(c[3])
        : "r"(a[0]), "r"(a[1]), "r"(a[2]), "r"(a[3]),
          "r"(b[0]), "r"(b[1]));
}
__device__ __forceinline__ void ldsm_x4(uint32_t* r, uint32_t saddr) {
    asm volatile(
        "ldmatrix.sync.aligned.m8n8.x4.shared.b16 {%0,%1,%2,%3}, [%4];"
        : "=r"(r[0]), "=r"(r[1]), "=r"(r[2]), "=r"(r[3]) : "r"(saddr));
}
__device__ __forceinline__ void ldsm_x4_t(uint32_t* r, uint32_t saddr) {
    asm volatile(
        "ldmatrix.sync.aligned.m8n8.x4.trans.shared.b16 {%0,%1,%2,%3}, [%4];"
        : "=r"(r[0]), "=r"(r[1]), "=r"(r[2]), "=r"(r[3]) : "r"(saddr));
}
__device__ __forceinline__ void cp_async16(uint32_t saddr, const void* gmem) {
    asm volatile("cp.async.cg.shared.global [%0], [%1], 16;\n" :: "r"(saddr), "l"(gmem));
}
__device__ __forceinline__ void cp_commit() {
    asm volatile("cp.async.commit_group;\n");
}
__device__ __forceinline__ void cp_wait1() {
    asm volatile("cp.async.wait_group 1;\n");
}

// ---------------------------------------------------------------------------
// fp16 tensor-core GEMM: C[M,N] = A[M,K] @ B.
// B_NT=true : B given as Bt[N,K] row-major (NT), ldmatrix non-trans.
// B_NT=false: B given as  B[K,N] row-major (NN), ldmatrix.trans.
// Epilogue EPI: 0 = +bias, 1 = +bias,GELU,
//               2 = exp(v/32) + per-row atomic sum into rsum (no bias).
// Optional rscale: per-row DIVISOR (softmax normalization in AV).
// Optional resid : fp32 [M,N] residual added AFTER bias/GELU/rscale.
// CTA tile 128x128, BK=64, 128 threads = 4 warps of 64x64, 2 CTAs/SM.
// 3-stage cp.async pipeline, ldmatrix.x4, register frag double-buffering.
// M,N multiples of 128; K multiple of 64, K/64 >= 2.
// ---------------------------------------------------------------------------
template <int EPI, bool OUT_HALF, bool B_NT>
__global__ void __launch_bounds__(128, 2)
gemm_h(const __half* __restrict__ A, const __half* __restrict__ Bm,
       const float* __restrict__ bias, const float* __restrict__ rscale,
       float* __restrict__ rsum, const float* __restrict__ resid,
       void* __restrict__ Cv,
       int M, int N, int K, int lda, int ldb,
       long long sA, long long sB, long long sC, long long sR)
{
    constexpr int BM = 128, BN = 128, BK = 64;
    constexpr int LDH2 = 36;                     // A smem pitch, u32 words
    constexpr int PB   = 68;                     // B smem pitch for NN, u32 words
    constexpr int A_STAGE = BM * LDH2;           // 4608 words
    constexpr int B_STAGE = B_NT ? (BN * LDH2)   // 4608 words (NT)
                                 : (BK * PB);    // 4352 words (NN)
    constexpr int STAGE   = A_STAGE + B_STAGE;

    extern __shared__ uint32_t smem_u[];
    const uint32_t sbase = (uint32_t)__cvta_generic_to_shared(smem_u);

    A  += (long long)blockIdx.z * sA;
    Bm += (long long)blockIdx.z * sB;
    if (rscale) rscale += (long long)blockIdx.z * sR;
    if (EPI == 2 && rsum) rsum += (long long)blockIdx.z * sR;
    if (resid) resid += (long long)blockIdx.z * sC;

    const int tid  = threadIdx.x;
    const int lane = tid & 31;
    const int wid  = tid >> 5;            // 0..3
    const int m0   = blockIdx.y * BM;
    const int n0   = blockIdx.x * BN;
    const int wm   = (wid & 1) * 64;      // 2 warps in M
    const int wn   = (wid >> 1) * 64;     // 2 warps in N
    const int lr   = lane >> 2;
    const int lc   = lane & 3;

    float acc[4][8][4];
    #pragma unroll
    for (int i = 0; i < 4; ++i)
        #pragma unroll
        for (int j = 0; j < 8; ++j)
            #pragma unroll
            for (int t = 0; t < 4; ++t)
                acc[i][j][t] = 0.0f;

    // ldmatrix per-lane byte offsets within a stage
    uint32_t a_off[4], b_off[4];
    {
        int arow  = wm + (lane & 15);
        int acol2 = (lane >> 4) * 4;
        #pragma unroll
        for (int mi = 0; mi < 4; ++mi)
            a_off[mi] = (uint32_t)(((arow + mi * 16) * LDH2 + acol2) * 4);

        if (B_NT) {
            int brow  = wn + (lane & 7) + ((lane >> 4) & 1) * 8;
            int bcol2 = ((lane >> 3) & 1) * 4;
            #pragma unroll
            for (int p = 0; p < 4; ++p)
                b_off[p] = (uint32_t)((A_STAGE + (brow + p * 16) * LDH2 + bcol2) * 4);
        } else {
            int mat   = lane >> 3;
            int krow  = (mat & 1) * 8 + (lane & 7);
            #pragma unroll
            for (int p = 0; p < 4; ++p) {
                int ncol = wn + p * 16 + (mat >> 1) * 8;
                b_off[p] = (uint32_t)(A_STAGE * 4 + krow * (PB * 4) + ncol * 2);
            }
        }
    }

    auto load_tile = [&](int t) {
        const uint32_t stg = sbase + (uint32_t)((t % 3) * STAGE * 4);
        const int k0 = t * BK;
        #pragma unroll
        for (int p = 0; p < 8; ++p) {
            int idx = tid + p * 128;
            int row = idx >> 3, ch = idx & 7;
            cp_async16(stg + (uint32_t)((row * LDH2 + ch * 4) * 4),
                       A + (long long)(m0 + row) * lda + k0 + ch * 8);
        }
        if (B_NT) {
            #pragma unroll
            for (int p = 0; p < 8; ++p) {
                int idx = tid + p * 128;
                int row = idx >> 3, ch = idx & 7;
                cp_async16(stg + (uint32_t)((A_STAGE + row * LDH2 + ch * 4) * 4),
                           Bm + (long long)(n0 + row) * ldb + k0 + ch * 8);
            }
        } else {
            #pragma unroll
            for (int p = 0; p < 8; ++p) {
                int idx = tid + p * 128;
                int row = idx >> 4, ch = idx & 15;
                cp_async16(stg + (uint32_t)(A_STAGE * 4 + row * (PB * 4) + ch * 16),
                           Bm + (long long)(k0 + row) * ldb + n0 + ch * 8);
            }
        }
    };

    uint32_t af[2][4][4], bf[2][8][2];
    auto load_frags = [&](uint32_t stg, int ks, int buf) {
        const uint32_t kbA = (uint32_t)(ks * 32);
        const uint32_t kbB = B_NT ? kbA : (uint32_t)(ks * 16 * PB * 4);
        #pragma unroll
        for (int mi = 0; mi < 4; ++mi)
            ldsm_x4(af[buf][mi], stg + a_off[mi] + kbA);
        #pragma unroll
        for (int p = 0; p < 4; ++p) {
            uint32_t r[4];
            if (B_NT) ldsm_x4  (r, stg + b_off[p] + kbB);
            else      ldsm_x4_t(r, stg + b_off[p] + kbB);
            bf[buf][2 * p + 0][0] = r[0];
            bf[buf][2 * p + 0][1] = r[1];
            bf[buf][2 * p + 1][0] = r[2];
            bf[buf][2 * p + 1][1] = r[3];
        }
    };

    const int NIT = K / BK;
    load_tile(0); cp_commit();
    load_tile(1); cp_commit();

    for (int it = 0; it < NIT; ++it) {
        cp_wait1();                 // stage `it` resident
        __syncthreads();            // all warps done reading stage (it+2)%3
        if (it + 2 < NIT) load_tile(it + 2);
        cp_commit();                // exactly one group per iteration

        const uint32_t stg = sbase + (uint32_t)((it % 3) * STAGE * 4);
        load_frags(stg, 0, 0);
        #pragma unroll
        for (int ks = 0; ks < 4; ++ks) {
            const int cur = ks & 1;
            if (ks < 3) load_frags(stg, ks + 1, cur ^ 1);
            #pragma unroll
            for (int mi = 0; mi < 4; ++mi)
                #pragma unroll
                for (int nj = 0; nj < 8; ++nj)
                    mma_f16(acc[mi][nj], af[cur][mi], bf[cur][nj]);
        }
    }

    // ---- epilogue ----
    float*  Cf = (float*) Cv + (long long)blockIdx.z * sC;
    __half* Ch = (__half*)Cv + (long long)blockIdx.z * sC;

    float rinv[4][2];
    if (rscale) {
        #pragma unroll
        for (int mi = 0; mi < 4; ++mi)
            #pragma unroll
            for (int hf = 0; hf < 2; ++hf)
                rinv[mi][hf] = 1.0f / rscale[m0 + wm + mi * 16 + lr + hf * 8];
    }

    float rowacc[4][2];
    if (EPI == 2) {
        #pragma unroll
        for (int mi = 0; mi < 4; ++mi) { rowacc[mi][0] = 0.0f; rowacc[mi][1] = 0.0f; }
    }

    #pragma unroll
    for (int mi = 0; mi < 4; ++mi) {
        #pragma unroll
        for (int nj = 0; nj < 8; ++nj) {
            const int col = n0 + wn + nj * 8 + lc * 2;
            float b0 = 0.0f, b1 = 0.0f;
            if (EPI != 2 && bias) { b0 = bias[col]; b1 = bias[col + 1]; }
            #pragma unroll
            for (int hf = 0; hf < 2; ++hf) {
                const int row = m0 + wm + mi * 16 + lr + hf * 8;
                float v0 = acc[mi][nj][hf * 2 + 0] + b0;
                float v1 = acc[mi][nj][hf * 2 + 1] + b1;
                if (EPI == 1) {
                    v0 = 0.5f * v0 * (1.0f + erff(v0 * 0.70710678118654752f));
                    v1 = 0.5f * v1 * (1.0f + erff(v1 * 0.70710678118654752f));
                } else if (EPI == 2) {
                    v0 = expf(v0 * 0.03125f);
                    v1 = expf(v1 * 0.03125f);
                    rowacc[mi][hf] += v0 + v1;
                }
                if (rscale) { v0 *= rinv[mi][hf]; v1 *= rinv[mi][hf]; }
                if (resid) {
                    float2 rv = *(const float2*)(resid + (long long)row * N + col);
                    v0 += rv.x; v1 += rv.y;
                }
                if (OUT_HALF) {
                    *(__half2*)(Ch + (long long)row * N + col) = __floats2half2_rn(v0, v1);
                } else {
                    *(float2*)(Cf + (long long)row * N + col) = make_float2(v0, v1);
                }
            }
        }
    }

    if (EPI == 2) {
        #pragma unroll
        for (int mi = 0; mi < 4; ++mi) {
            #pragma unroll
            for (int hf = 0; hf < 2; ++hf) {
                float s = rowacc[mi][hf];
                s += __shfl_xor_sync(0xffffffffu, s, 1);
                s += __shfl_xor_sync(0xffffffffu, s, 2);
                if (lc == 0)
                    atomicAdd(&rsum[m0 + wm + mi * 16 + lr + hf * 8], s);
            }
        }
    }
}

// ---------------------------------------------------------------------------
// Elementwise fp32 -> half
// ---------------------------------------------------------------------------
__global__ void __launch_bounds__(256)
f2h_kernel(const float4* __restrict__ in, __half2* __restrict__ out, long long n4)
{
    long long i = (long long)blockIdx.x * blockDim.x + threadIdx.x;
    long long stride = (long long)gridDim.x * blockDim.x;
    for (; i < n4; i += stride) {
        float4 v = in[i];
        out[2 * i + 0] = __floats2half2_rn(v.x, v.y);
        out[2 * i + 1] = __floats2half2_rn(v.z, v.w);
    }
}

// ---------------------------------------------------------------------------
// Batched transpose fp32 [D][D] -> half [D][D]^T for 3 weight matrices (z sel)
// ---------------------------------------------------------------------------
__global__ void __launch_bounds__(256)
transpose_f2h3(const float* __restrict__ w0, const float* __restrict__ w1,
               const float* __restrict__ w2, __half* __restrict__ out)
{
    __shared__ float t[32][33];
    const float* in = (blockIdx.z == 0) ? w0 : (blockIdx.z == 1) ? w1 : w2;
    __half* o = out + (long long)blockIdx.z * DD * DD;
    int x = blockIdx.x * 32 + threadIdx.x;
    int y = blockIdx.y * 32 + threadIdx.y;
    #pragma unroll
    for (int i = 0; i < 32; i += 8)
        t[threadIdx.y + i][threadIdx.x] = in[(long long)(y + i) * DD + x];
    __syncthreads();
    x = blockIdx.y * 32 + threadIdx.x;
    y = blockIdx.x * 32 + threadIdx.y;
    #pragma unroll
    for (int i = 0; i < 32; i += 8)
        o[(long long)(y + i) * DD + x] = __float2half_rn(t[threadIdx.x][threadIdx.y + i]);
}

// ---------------------------------------------------------------------------
// Transpose fp32 [R][C] -> half [C][R]
// ---------------------------------------------------------------------------
__global__ void __launch_bounds__(256)
transpose_f2h(const float* __restrict__ in, __half* __restrict__ out, int R, int C)
{
    __shared__ float t[32][33];
    int x = blockIdx.x * 32 + threadIdx.x;
    int y = blockIdx.y * 32 + threadIdx.y;
    #pragma unroll
    for (int i = 0; i < 32; i += 8)
        t[threadIdx.y + i][threadIdx.x] = in[(long long)(y + i) * C + x];
    __syncthreads();
    x = blockIdx.y * 32 + threadIdx.x;
    y = blockIdx.x * 32 + threadIdx.y;
    #pragma unroll
    for (int i = 0; i < 32; i += 8)
        out[(long long)(y + i) * R + x] = __float2half_rn(t[threadIdx.x][threadIdx.y + i]);
}

// ---------------------------------------------------------------------------
// Block reduction helper (sum or max), 256 threads
// ---------------------------------------------------------------------------
__device__ __forceinline__ float block_reduce(float v, bool do_max) {
    __shared__ float sh[33];
    #pragma unroll
    for (int o = 16; o > 0; o >>= 1) {
        float t = __shfl_xor_sync(0xffffffffu, v, o);
        v = do_max ? fmaxf(v, t) : (v + t);
    }
    const int lane = threadIdx.x & 31;
    const int wid  = threadIdx.x >> 5;
    if (lane == 0) sh[wid] = v;
    __syncthreads();
    if (wid == 0) {
        int nw = blockDim.x >> 5;
        v = (lane < nw) ? sh[lane] : (do_max ? -INFINITY : 0.0f);
        #pragma unroll
        for (int o = 16; o > 0; o >>= 1) {
            float t = __shfl_xor_sync(0xffffffffu, v, o);
            v = do_max ? fmaxf(v, t) : (v + t);
        }
        if (lane == 0) sh[32] = v;
    }
    __syncthreads();
    float r = sh[32];
    __syncthreads();
    return r;
}

// ---------------------------------------------------------------------------
// out = LayerNorm(X [+ R]) * gamma + beta; fp32 out, optional half copy.
// R may be nullptr (input already contains the residual sum).
// ---------------------------------------------------------------------------
__global__ void __launch_bounds__(256)
add_ln_kernel(const float* __restrict__ X, const float* __restrict__ R,
              const float* __restrict__ gamma, const float* __restrict__ beta,
              float* __restrict__ O, __half* __restrict__ Oh)
{
    constexpr int D = DD;
    const long long base = (long long)blockIdx.x * D;
    const int d = threadIdx.x * 4;

    float4 v = *(const float4*)(X + base + d);
    if (R) {
        float4 rv = *(const float4*)(R + base + d);
        v.x += rv.x; v.y += rv.y; v.z += rv.z; v.w += rv.w;
    }

    float mean = block_reduce(v.x + v.y + v.z + v.w, false) * (1.0f / D);

    float4 dv = make_float4(v.x - mean, v.y - mean, v.z - mean, v.w - mean);
    float var = block_reduce(dv.x * dv.x + dv.y * dv.y + dv.z * dv.z + dv.w * dv.w,
                             false) * (1.0f / D);
    float inv = rsqrtf(var + 1e-5f);

    float4 gv = *(const float4*)(gamma + d);
    float4 bv = *(const float4*)(beta + d);
    float4 o;
    o.x = dv.x * inv * gv.x + bv.x;
    o.y = dv.y * inv * gv.y + bv.y;
    o.z = dv.z * inv * gv.z + bv.z;
    o.w = dv.w * inv * gv.w + bv.w;
    *(float4*)(O + base + d) = o;
    if (Oh) {
        *(__half2*)(Oh + base + d)     = __floats2half2_rn(o.x, o.y);
        *(__half2*)(Oh + base + d + 2) = __floats2half2_rn(o.z, o.w);
    }
}

// ---------------------------------------------------------------------------
// kernel_launch
// Inputs: input_embedding, Wq, bq, Wk, bk, Wv, bv, W1, b1, W2, b2, gamma, beta
// Launch order keeps the scores GEMM at kernel-launch #4 (ncu captures it).
// ---------------------------------------------------------------------------
extern "C" void kernel_launch(void* const* d_in, const int* /*in_sizes*/, int /*n_in*/,
                              void* d_out, int /*out_size*/)
{
    const float* x     = (const float*)d_in[0];
    const float* Wq    = (const float*)d_in[1];
    const float* bq    = (const float*)d_in[2];
    const float* Wk    = (const float*)d_in[3];
    const float* bk    = (const float*)d_in[4];
    const float* Wv    = (const float*)d_in[5];
    const float* bv    = (const float*)d_in[6];
    const float* W1    = (const float*)d_in[7];
    const float* b1    = (const float*)d_in[8];
    const float* W2    = (const float*)d_in[9];
    const float* b2    = (const float*)d_in[10];
    const float* gamma = (const float*)d_in[11];
    const float* beta  = (const float*)d_in[12];
    float* out = (float*)d_out;

    __half *xh, *wqkvT, *w1T, *w2T, *qkv, *at, *x1h, *hh;
    float *bqkv, *rs, *ao, *x1f, *ff;
    cudaGetSymbolAddress((void**)&xh,    g_xh);
    cudaGetSymbolAddress((void**)&wqkvT, g_wqkvT);
    cudaGetSymbolAddress((void**)&bqkv,  g_bqkv);
    cudaGetSymbolAddress((void**)&w1T,   g_w1T);
    cudaGetSymbolAddress((void**)&w2T,   g_w2T);
    cudaGetSymbolAddress((void**)&qkv,   g_qkv);
    cudaGetSymbolAddress((void**)&at,    g_at);
    cudaGetSymbolAddress((void**)&rs,    g_rs);
    cudaGetSymbolAddress((void**)&ao,    g_ao);
    cudaGetSymbolAddress((void**)&x1f,   g_x1f);
    cudaGetSymbolAddress((void**)&x1h,   g_x1h);
    cudaGetSymbolAddress((void**)&hh,    g_hh);
    cudaGetSymbolAddress((void**)&ff,    g_ff);

    const int SMEM = 3 * 9216 * 4;   // 110592 B per CTA (2 CTAs/SM), covers both paths
    cudaFuncSetAttribute((const void*)gemm_h<0, true,  true>,
                         cudaFuncAttributeMaxDynamicSharedMemorySize, SMEM);
    cudaFuncSetAttribute((const void*)gemm_h<2, true,  true>,
                         cudaFuncAttributeMaxDynamicSharedMemorySize, SMEM);
    cudaFuncSetAttribute((const void*)gemm_h<0, false, false>,
                         cudaFuncAttributeMaxDynamicSharedMemorySize, SMEM);
    cudaFuncSetAttribute((const void*)gemm_h<1, true,  true>,
                         cudaFuncAttributeMaxDynamicSharedMemorySize, SMEM);
    cudaFuncSetAttribute((const void*)gemm_h<0, false, true>,
                         cudaFuncAttributeMaxDynamicSharedMemorySize, SMEM);

    dim3 gblk(128);          // gemm CTAs: 4 warps
    dim3 blk(256);
    dim3 tblk(32, 8);

    // --- prep (launches 1-2) + zero rowsum accumulator ---
    f2h_kernel<<<1184, blk>>>((const float4*)x, (__half2*)xh, (long long)MM * DD / 4);
    transpose_f2h3<<<dim3(DD/32, DD/32, 3), tblk>>>(Wq, Wk, Wv, wqkvT);
    cudaMemsetAsync(rs, 0, MM * sizeof(float));
    cudaMemcpyAsync(bqkv,          bq, DD * sizeof(float), cudaMemcpyDeviceToDevice);
    cudaMemcpyAsync(bqkv + DD,     bk, DD * sizeof(float), cudaMemcpyDeviceToDevice);
    cudaMemcpyAsync(bqkv + 2 * DD, bv, DD * sizeof(float), cudaMemcpyDeviceToDevice);

    // --- fused QKV projection (launch 3) ---
    dim3 gqkv(3 * DD / 128, MM / 128, 1);
    gemm_h<0, true, true><<<gqkv, gblk, SMEM>>>(
        xh, wqkvT, bqkv, nullptr, nullptr, nullptr, qkv,
        MM, 3 * DD, DD, DD, DD, 0, 0, 0, 0);

    const __half* qh = qkv;
    const __half* kh = qkv + DD;
    const __half* vh = qkv + 2 * DD;

    // --- at[b] = exp(k[b] @ q[b]^T / 32), rowsums via atomics (launch 4) ---
    dim3 gsc(SS / 128, SS / 128, BB);
    gemm_h<2, true, true><<<gsc, gblk, SMEM>>>(
        kh, qh, nullptr, nullptr, rs, nullptr, at, SS, SS, DD, 3 * DD, 3 * DD,
        (long long)SS * 3 * DD, (long long)SS * 3 * DD, (long long)SS * SS, SS);

    // --- remaining weight transposes ---
    transpose_f2h<<<dim3(HH/32, DD/32), tblk>>>(W1, w1T, DD, HH);
    transpose_f2h<<<dim3(DD/32, HH/32), tblk>>>(W2, w2T, HH, DD);

    // --- ao[b] = x[b] + (at[b] @ v[b]) / rs  (NN path + fused residual) ---
    dim3 gav(DD / 128, SS / 128, BB);
    gemm_h<0, false, false><<<gav, gblk, SMEM>>>(
        at, vh, nullptr, rs, nullptr, x, ao, SS, DD, SS, SS, 3 * DD,
        (long long)SS * SS, (long long)SS * 3 * DD, (long long)SS * DD, SS);

    // --- x1 = LayerNorm(ao); fp32 + half ---
    add_ln_kernel<<<MM, blk>>>(ao, nullptr, gamma, beta, x1f, x1h);

    // --- h = gelu(x1 @ W1 + b1), half out ---
    dim3 gf1(HH / 128, MM / 128, 1);
    gemm_h<1, true, true><<<gf1, gblk, SMEM>>>(
        x1h, w1T, b1, nullptr, nullptr, nullptr, hh,
        MM, HH, DD, DD, DD, 0, 0, 0, 0);

    // --- ff = x1 + (h @ W2 + b2), fp32 out (fused residual) ---
    dim3 gf2(DD / 128, MM / 128, 1);
    gemm_h<0, false, true><<<gf2, gblk, SMEM>>>(
        hh, w2T, b2, nullptr, nullptr, x1f, ff,
        MM, DD, HH, HH, HH, 0, 0, 0, 0);

    // --- out = LayerNorm(ff), fp32 ---
    add_ln_kernel<<<MM, blk>>>(ff, nullptr, gamma, beta, out, nullptr);
}

// round 16
// speedup vs baseline: 1.0182x; 1.0182x over previous
#include <cuda_runtime.h>
#include <cuda_fp16.h>
#include <math.h>
#include <stdint.h>

// ---------------------------------------------------------------------------
// B=2, S=4096, D=1024, H=4096, M=B*S=8192
// ---------------------------------------------------------------------------
#define BB   2
#define SS   4096
#define DD   1024
#define HH   4096
#define MM   (BB * SS)

// ---------------------------------------------------------------------------
// Scratch (static device globals; no runtime allocation allowed)
// ---------------------------------------------------------------------------
__device__ __half g_xh   [MM * DD];
__device__ __half g_wqkvT[3 * DD * DD];
__device__ float  g_bqkv [3 * DD];
__device__ __half g_w1T  [(long long)HH * DD];
__device__ __half g_w2T  [(long long)DD * HH];
__device__ __half g_qkv  [(long long)MM * 3 * DD];
__device__ __half g_at   [(long long)BB * SS * SS];   // exp(logits/32), half
__device__ float  g_rs   [MM];                        // rowsum of exp (atomic)
__device__ __half g_aoh  [MM * DD];                   // attn_out, half
__device__ __half g_x1h  [MM * DD];                   // LN1 output, half
__device__ __half g_hh   [(long long)MM * HH];
__device__ float  g_ff   [MM * DD];

// ---------------------------------------------------------------------------
// PTX helpers
// ---------------------------------------------------------------------------
__device__ __forceinline__ void mma_f16(float* c, const uint32_t* a, const uint32_t* b) {
    asm volatile(
        "mma.sync.aligned.m16n8k16.row.col.f32.f16.f16.f32 "
        "{%0,%1,%2,%3}, {%4,%5,%6,%7}, {%8,%9}, {%0,%1,%2,%3};\n"
        : "+f"(c[0]), "+f"(c[1]), "+f"(c[2]), "+f"(c[3])
        : "r"(a[0]), "r"(a[1]), "r"(a[2]), "r"(a[3]),
          "r"(b[0]), "r"(b[1]));
}
__device__ __forceinline__ void ldsm_x4(uint32_t* r, uint32_t saddr) {
    asm volatile(
        "ldmatrix.sync.aligned.m8n8.x4.shared.b16 {%0,%1,%2,%3}, [%4];"
        : "=r"(r[0]), "=r"(r[1]), "=r"(r[2]), "=r"(r[3]) : "r"(saddr));
}
__device__ __forceinline__ void ldsm_x4_t(uint32_t* r, uint32_t saddr) {
    asm volatile(
        "ldmatrix.sync.aligned.m8n8.x4.trans.shared.b16 {%0,%1,%2,%3}, [%4];"
        : "=r"(r[0]), "=r"(r[1]), "=r"(r[2]), "=r"(r[3]) : "r"(saddr));
}
__device__ __forceinline__ void cp_async16(uint32_t saddr, const void* gmem) {
    asm volatile("cp.async.cg.shared.global [%0], [%1], 16;\n" :: "r"(saddr), "l"(gmem));
}
__device__ __forceinline__ void cp_commit() {
    asm volatile("cp.async.commit_group;\n");
}
__device__ __forceinline__ void cp_wait1() {
    asm volatile("cp.async.wait_group 1;\n");
}

// ---------------------------------------------------------------------------
// fp16 tensor-core GEMM: C[M,N] = A[M,K] @ B.   (round-14 structure, verbatim)
// B_NT=true : B given as Bt[N,K] row-major (NT), ldmatrix non-trans.
// B_NT=false: B given as  B[K,N] row-major (NN), ldmatrix.trans.
// Epilogue EPI: 0 = +bias, 1 = +bias,GELU,
//               2 = exp(v/32) + per-row atomic sum into rsum (no bias).
// Optional rscale: per-row DIVISOR (softmax normalization in AV).
// CTA tile 128x128, BK=64, 128 threads = 4 warps of 64x64, 2 CTAs/SM.
// 3-stage cp.async pipeline, ldmatrix.x4, register frag double-buffering.
// M,N multiples of 128; K multiple of 64, K/64 >= 2.
// ---------------------------------------------------------------------------
template <int EPI, bool OUT_HALF, bool B_NT>
__global__ void __launch_bounds__(128, 2)
gemm_h(const __half* __restrict__ A, const __half* __restrict__ Bm,
       const float* __restrict__ bias, const float* __restrict__ rscale,
       float* __restrict__ rsum, void* __restrict__ Cv,
       int M, int N, int K, int lda, int ldb,
       long long sA, long long sB, long long sC, long long sR)
{
    constexpr int BM = 128, BN = 128, BK = 64;
    constexpr int LDH2 = 36;                     // A smem pitch, u32 words
    constexpr int PB   = 68;                     // B smem pitch for NN, u32 words
    constexpr int A_STAGE = BM * LDH2;           // 4608 words
    constexpr int B_STAGE = B_NT ? (BN * LDH2)   // 4608 words (NT)
                                 : (BK * PB);    // 4352 words (NN)
    constexpr int STAGE   = A_STAGE + B_STAGE;

    extern __shared__ uint32_t smem_u[];
    const uint32_t sbase = (uint32_t)__cvta_generic_to_shared(smem_u);

    A  += (long long)blockIdx.z * sA;
    Bm += (long long)blockIdx.z * sB;
    if (rscale) rscale += (long long)blockIdx.z * sR;
    if (EPI == 2 && rsum) rsum += (long long)blockIdx.z * sR;

    const int tid  = threadIdx.x;
    const int lane = tid & 31;
    const int wid  = tid >> 5;            // 0..3
    const int m0   = blockIdx.y * BM;
    const int n0   = blockIdx.x * BN;
    const int wm   = (wid & 1) * 64;      // 2 warps in M
    const int wn   = (wid >> 1) * 64;     // 2 warps in N
    const int lr   = lane >> 2;
    const int lc   = lane & 3;

    float acc[4][8][4];
    #pragma unroll
    for (int i = 0; i < 4; ++i)
        #pragma unroll
        for (int j = 0; j < 8; ++j)
            #pragma unroll
            for (int t = 0; t < 4; ++t)
                acc[i][j][t] = 0.0f;

    // ldmatrix per-lane byte offsets within a stage
    uint32_t a_off[4], b_off[4];
    {
        int arow  = wm + (lane & 15);
        int acol2 = (lane >> 4) * 4;
        #pragma unroll
        for (int mi = 0; mi < 4; ++mi)
            a_off[mi] = (uint32_t)(((arow + mi * 16) * LDH2 + acol2) * 4);

        if (B_NT) {
            int brow  = wn + (lane & 7) + ((lane >> 4) & 1) * 8;
            int bcol2 = ((lane >> 3) & 1) * 4;
            #pragma unroll
            for (int p = 0; p < 4; ++p)
                b_off[p] = (uint32_t)((A_STAGE + (brow + p * 16) * LDH2 + bcol2) * 4);
        } else {
            int mat   = lane >> 3;
            int krow  = (mat & 1) * 8 + (lane & 7);
            #pragma unroll
            for (int p = 0; p < 4; ++p) {
                int ncol = wn + p * 16 + (mat >> 1) * 8;
                b_off[p] = (uint32_t)(A_STAGE * 4 + krow * (PB * 4) + ncol * 2);
            }
        }
    }

    auto load_tile = [&](int t) {
        const uint32_t stg = sbase + (uint32_t)((t % 3) * STAGE * 4);
        const int k0 = t * BK;
        #pragma unroll
        for (int p = 0; p < 8; ++p) {
            int idx = tid + p * 128;
            int row = idx >> 3, ch = idx & 7;
            cp_async16(stg + (uint32_t)((row * LDH2 + ch * 4) * 4),
                       A + (long long)(m0 + row) * lda + k0 + ch * 8);
        }
        if (B_NT) {
            #pragma unroll
            for (int p = 0; p < 8; ++p) {
                int idx = tid + p * 128;
                int row = idx >> 3, ch = idx & 7;
                cp_async16(stg + (uint32_t)((A_STAGE + row * LDH2 + ch * 4) * 4),
                           Bm + (long long)(n0 + row) * ldb + k0 + ch * 8);
            }
        } else {
            #pragma unroll
            for (int p = 0; p < 8; ++p) {
                int idx = tid + p * 128;
                int row = idx >> 4, ch = idx & 15;
                cp_async16(stg + (uint32_t)(A_STAGE * 4 + row * (PB * 4) + ch * 16),
                           Bm + (long long)(k0 + row) * ldb + n0 + ch * 8);
            }
        }
    };

    uint32_t af[2][4][4], bf[2][8][2];
    auto load_frags = [&](uint32_t stg, int ks, int buf) {
        const uint32_t kbA = (uint32_t)(ks * 32);
        const uint32_t kbB = B_NT ? kbA : (uint32_t)(ks * 16 * PB * 4);
        #pragma unroll
        for (int mi = 0; mi < 4; ++mi)
            ldsm_x4(af[buf][mi], stg + a_off[mi] + kbA);
        #pragma unroll
        for (int p = 0; p < 4; ++p) {
            uint32_t r[4];
            if (B_NT) ldsm_x4  (r, stg + b_off[p] + kbB);
            else      ldsm_x4_t(r, stg + b_off[p] + kbB);
            bf[buf][2 * p + 0][0] = r[0];
            bf[buf][2 * p + 0][1] = r[1];
            bf[buf][2 * p + 1][0] = r[2];
            bf[buf][2 * p + 1][1] = r[3];
        }
    };

    const int NIT = K / BK;
    load_tile(0); cp_commit();
    load_tile(1); cp_commit();

    for (int it = 0; it < NIT; ++it) {
        cp_wait1();                 // stage `it` resident
        __syncthreads();            // all warps done reading stage (it+2)%3
        if (it + 2 < NIT) load_tile(it + 2);
        cp_commit();                // exactly one group per iteration

        const uint32_t stg = sbase + (uint32_t)((it % 3) * STAGE * 4);
        load_frags(stg, 0, 0);
        #pragma unroll
        for (int ks = 0; ks < 4; ++ks) {
            const int cur = ks & 1;
            if (ks < 3) load_frags(stg, ks + 1, cur ^ 1);
            #pragma unroll
            for (int mi = 0; mi < 4; ++mi)
                #pragma unroll
                for (int nj = 0; nj < 8; ++nj)
                    mma_f16(acc[mi][nj], af[cur][mi], bf[cur][nj]);
        }
    }

    // ---- epilogue ----
    float*  Cf = (float*) Cv + (long long)blockIdx.z * sC;
    __half* Ch = (__half*)Cv + (long long)blockIdx.z * sC;

    float rinv[4][2];
    if (rscale) {
        #pragma unroll
        for (int mi = 0; mi < 4; ++mi)
            #pragma unroll
            for (int hf = 0; hf < 2; ++hf)
                rinv[mi][hf] = 1.0f / rscale[m0 + wm + mi * 16 + lr + hf * 8];
    }

    float rowacc[4][2];
    if (EPI == 2) {
        #pragma unroll
        for (int mi = 0; mi < 4; ++mi) { rowacc[mi][0] = 0.0f; rowacc[mi][1] = 0.0f; }
    }

    #pragma unroll
    for (int mi = 0; mi < 4; ++mi) {
        #pragma unroll
        for (int nj = 0; nj < 8; ++nj) {
            const int col = n0 + wn + nj * 8 + lc * 2;
            float b0 = 0.0f, b1 = 0.0f;
            if (EPI != 2 && bias) { b0 = bias[col]; b1 = bias[col + 1]; }
            #pragma unroll
            for (int hf = 0; hf < 2; ++hf) {
                const int row = m0 + wm + mi * 16 + lr + hf * 8;
                float v0 = acc[mi][nj][hf * 2 + 0] + b0;
                float v1 = acc[mi][nj][hf * 2 + 1] + b1;
                if (EPI == 1) {
                    v0 = 0.5f * v0 * (1.0f + erff(v0 * 0.70710678118654752f));
                    v1 = 0.5f * v1 * (1.0f + erff(v1 * 0.70710678118654752f));
                } else if (EPI == 2) {
                    v0 = expf(v0 * 0.03125f);
                    v1 = expf(v1 * 0.03125f);
                    rowacc[mi][hf] += v0 + v1;
                }
                if (rscale) { v0 *= rinv[mi][hf]; v1 *= rinv[mi][hf]; }
                if (OUT_HALF) {
                    *(__half2*)(Ch + (long long)row * N + col) = __floats2half2_rn(v0, v1);
                } else {
                    *(float2*)(Cf + (long long)row * N + col) = make_float2(v0, v1);
                }
            }
        }
    }

    if (EPI == 2) {
        #pragma unroll
        for (int mi = 0; mi < 4; ++mi) {
            #pragma unroll
            for (int hf = 0; hf < 2; ++hf) {
                float s = rowacc[mi][hf];
                s += __shfl_xor_sync(0xffffffffu, s, 1);
                s += __shfl_xor_sync(0xffffffffu, s, 2);
                if (lc == 0)
                    atomicAdd(&rsum[m0 + wm + mi * 16 + lr + hf * 8], s);
            }
        }
    }
}

// ---------------------------------------------------------------------------
// Elementwise fp32 -> half
// ---------------------------------------------------------------------------
__global__ void __launch_bounds__(256)
f2h_kernel(const float4* __restrict__ in, __half2* __restrict__ out, long long n4)
{
    long long i = (long long)blockIdx.x * blockDim.x + threadIdx.x;
    long long stride = (long long)gridDim.x * blockDim.x;
    for (; i < n4; i += stride) {
        float4 v = in[i];
        out[2 * i + 0] = __floats2half2_rn(v.x, v.y);
        out[2 * i + 1] = __floats2half2_rn(v.z, v.w);
    }
}

// ---------------------------------------------------------------------------
// Batched transpose fp32 [D][D] -> half [D][D]^T for 3 weight matrices (z sel)
// ---------------------------------------------------------------------------
__global__ void __launch_bounds__(256)
transpose_f2h3(const float* __restrict__ w0, const float* __restrict__ w1,
               const float* __restrict__ w2, __half* __restrict__ out)
{
    __shared__ float t[32][33];
    const float* in = (blockIdx.z == 0) ? w0 : (blockIdx.z == 1) ? w1 : w2;
    __half* o = out + (long long)blockIdx.z * DD * DD;
    int x = blockIdx.x * 32 + threadIdx.x;
    int y = blockIdx.y * 32 + threadIdx.y;
    #pragma unroll
    for (int i = 0; i < 32; i += 8)
        t[threadIdx.y + i][threadIdx.x] = in[(long long)(y + i) * DD + x];
    __syncthreads();
    x = blockIdx.y * 32 + threadIdx.x;
    y = blockIdx.x * 32 + threadIdx.y;
    #pragma unroll
    for (int i = 0; i < 32; i += 8)
        o[(long long)(y + i) * DD + x] = __float2half_rn(t[threadIdx.x][threadIdx.y + i]);
}

// ---------------------------------------------------------------------------
// Transpose fp32 [R][C] -> half [C][R]
// ---------------------------------------------------------------------------
__global__ void __launch_bounds__(256)
transpose_f2h(const float* __restrict__ in, __half* __restrict__ out, int R, int C)
{
    __shared__ float t[32][33];
    int x = blockIdx.x * 32 + threadIdx.x;
    int y = blockIdx.y * 32 + threadIdx.y;
    #pragma unroll
    for (int i = 0; i < 32; i += 8)
        t[threadIdx.y + i][threadIdx.x] = in[(long long)(y + i) * C + x];
    __syncthreads();
    x = blockIdx.y * 32 + threadIdx.x;
    y = blockIdx.x * 32 + threadIdx.y;
    #pragma unroll
    for (int i = 0; i < 32; i += 8)
        out[(long long)(y + i) * R + x] = __float2half_rn(t[threadIdx.x][threadIdx.y + i]);
}

// ---------------------------------------------------------------------------
// Block reduction helper (sum or max), 256 threads
// ---------------------------------------------------------------------------
__device__ __forceinline__ float block_reduce(float v, bool do_max) {
    __shared__ float sh[33];
    #pragma unroll
    for (int o = 16; o > 0; o >>= 1) {
        float t = __shfl_xor_sync(0xffffffffu, v, o);
        v = do_max ? fmaxf(v, t) : (v + t);
    }
    const int lane = threadIdx.x & 31;
    const int wid  = threadIdx.x >> 5;
    if (lane == 0) sh[wid] = v;
    __syncthreads();
    if (wid == 0) {
        int nw = blockDim.x >> 5;
        v = (lane < nw) ? sh[lane] : (do_max ? -INFINITY : 0.0f);
        #pragma unroll
        for (int o = 16; o > 0; o >>= 1) {
            float t = __shfl_xor_sync(0xffffffffu, v, o);
            v = do_max ? fmaxf(v, t) : (v + t);
        }
        if (lane == 0) sh[32] = v;
    }
    __syncthreads();
    float r = sh[32];
    __syncthreads();
    return r;
}

// ---------------------------------------------------------------------------
// LayerNorm with mixed inputs: v = Xf (fp32) + Xh (half).
// Outputs: Of (fp32, optional), Oh (half, optional).
// One block per row of D=1024, 256 threads, 4 elems/thread.
// ---------------------------------------------------------------------------
__global__ void __launch_bounds__(256)
ln_mix_kernel(const float* __restrict__ Xf, const __half* __restrict__ Xh,
              const float* __restrict__ gamma, const float* __restrict__ beta,
              float* __restrict__ Of, __half* __restrict__ Oh)
{
    constexpr int D = DD;
    const long long base = (long long)blockIdx.x * D;
    const int d = threadIdx.x * 4;

    float4 v = *(const float4*)(Xf + base + d);
    {
        float2 f0 = __half22float2(*(const __half2*)(Xh + base + d));
        float2 f1 = __half22float2(*(const __half2*)(Xh + base + d + 2));
        v.x += f0.x; v.y += f0.y; v.z += f1.x; v.w += f1.y;
    }

    float mean = block_reduce(v.x + v.y + v.z + v.w, false) * (1.0f / D);

    float4 dv = make_float4(v.x - mean, v.y - mean, v.z - mean, v.w - mean);
    float var = block_reduce(dv.x * dv.x + dv.y * dv.y + dv.z * dv.z + dv.w * dv.w,
                             false) * (1.0f / D);
    float inv = rsqrtf(var + 1e-5f);

    float4 gv = *(const float4*)(gamma + d);
    float4 bv = *(const float4*)(beta + d);
    float4 o;
    o.x = dv.x * inv * gv.x + bv.x;
    o.y = dv.y * inv * gv.y + bv.y;
    o.z = dv.z * inv * gv.z + bv.z;
    o.w = dv.w * inv * gv.w + bv.w;
    if (Of) *(float4*)(Of + base + d) = o;
    if (Oh) {
        *(__half2*)(Oh + base + d)     = __floats2half2_rn(o.x, o.y);
        *(__half2*)(Oh + base + d + 2) = __floats2half2_rn(o.z, o.w);
    }
}

// ---------------------------------------------------------------------------
// kernel_launch
// Inputs: input_embedding, Wq, bq, Wk, bk, Wv, bv, W1, b1, W2, b2, gamma, beta
// Launch order keeps the scores GEMM at kernel-launch #4 (ncu captures it).
// ---------------------------------------------------------------------------
extern "C" void kernel_launch(void* const* d_in, const int* /*in_sizes*/, int /*n_in*/,
                              void* d_out, int /*out_size*/)
{
    const float* x     = (const float*)d_in[0];
    const float* Wq    = (const float*)d_in[1];
    const float* bq    = (const float*)d_in[2];
    const float* Wk    = (const float*)d_in[3];
    const float* bk    = (const float*)d_in[4];
    const float* Wv    = (const float*)d_in[5];
    const float* bv    = (const float*)d_in[6];
    const float* W1    = (const float*)d_in[7];
    const float* b1    = (const float*)d_in[8];
    const float* W2    = (const float*)d_in[9];
    const float* b2    = (const float*)d_in[10];
    const float* gamma = (const float*)d_in[11];
    const float* beta  = (const float*)d_in[12];
    float* out = (float*)d_out;

    __half *xh, *wqkvT, *w1T, *w2T, *qkv, *at, *aoh, *x1h, *hh;
    float *bqkv, *rs, *ff;
    cudaGetSymbolAddress((void**)&xh,    g_xh);
    cudaGetSymbolAddress((void**)&wqkvT, g_wqkvT);
    cudaGetSymbolAddress((void**)&bqkv,  g_bqkv);
    cudaGetSymbolAddress((void**)&w1T,   g_w1T);
    cudaGetSymbolAddress((void**)&w2T,   g_w2T);
    cudaGetSymbolAddress((void**)&qkv,   g_qkv);
    cudaGetSymbolAddress((void**)&at,    g_at);
    cudaGetSymbolAddress((void**)&rs,    g_rs);
    cudaGetSymbolAddress((void**)&aoh,   g_aoh);
    cudaGetSymbolAddress((void**)&x1h,   g_x1h);
    cudaGetSymbolAddress((void**)&hh,    g_hh);
    cudaGetSymbolAddress((void**)&ff,    g_ff);

    const int SMEM = 3 * 9216 * 4;   // 110592 B per CTA (2 CTAs/SM), covers both paths
    cudaFuncSetAttribute((const void*)gemm_h<0, true,  true>,
                         cudaFuncAttributeMaxDynamicSharedMemorySize, SMEM);
    cudaFuncSetAttribute((const void*)gemm_h<2, true,  true>,
                         cudaFuncAttributeMaxDynamicSharedMemorySize, SMEM);
    cudaFuncSetAttribute((const void*)gemm_h<0, true,  false>,
                         cudaFuncAttributeMaxDynamicSharedMemorySize, SMEM);
    cudaFuncSetAttribute((const void*)gemm_h<1, true,  true>,
                         cudaFuncAttributeMaxDynamicSharedMemorySize, SMEM);
    cudaFuncSetAttribute((const void*)gemm_h<0, false, true>,
                         cudaFuncAttributeMaxDynamicSharedMemorySize, SMEM);

    dim3 gblk(128);          // gemm CTAs: 4 warps
    dim3 blk(256);
    dim3 tblk(32, 8);

    // --- prep (launches 1-2) + zero rowsum accumulator ---
    f2h_kernel<<<1184, blk>>>((const float4*)x, (__half2*)xh, (long long)MM * DD / 4);
    transpose_f2h3<<<dim3(DD/32, DD/32, 3), tblk>>>(Wq, Wk, Wv, wqkvT);
    cudaMemsetAsync(rs, 0, MM * sizeof(float));
    cudaMemcpyAsync(bqkv,          bq, DD * sizeof(float), cudaMemcpyDeviceToDevice);
    cudaMemcpyAsync(bqkv + DD,     bk, DD * sizeof(float), cudaMemcpyDeviceToDevice);
    cudaMemcpyAsync(bqkv + 2 * DD, bv, DD * sizeof(float), cudaMemcpyDeviceToDevice);

    // --- fused QKV projection (launch 3) ---
    dim3 gqkv(3 * DD / 128, MM / 128, 1);
    gemm_h<0, true, true><<<gqkv, gblk, SMEM>>>(
        xh, wqkvT, bqkv, nullptr, nullptr, qkv,
        MM, 3 * DD, DD, DD, DD, 0, 0, 0, 0);

    const __half* qh = qkv;
    const __half* kh = qkv + DD;
    const __half* vh = qkv + 2 * DD;

    // --- at[b] = exp(k[b] @ q[b]^T / 32), rowsums via atomics (launch 4) ---
    dim3 gsc(SS / 128, SS / 128, BB);
    gemm_h<2, true, true><<<gsc, gblk, SMEM>>>(
        kh, qh, nullptr, nullptr, rs, at, SS, SS, DD, 3 * DD, 3 * DD,
        (long long)SS * 3 * DD, (long long)SS * 3 * DD, (long long)SS * SS, SS);

    // --- remaining weight transposes ---
    transpose_f2h<<<dim3(HH/32, DD/32), tblk>>>(W1, w1T, DD, HH);
    transpose_f2h<<<dim3(DD/32, HH/32), tblk>>>(W2, w2T, HH, DD);

    // --- aoh[b] = (at[b] @ v[b]) / rs  (NN path, HALF out) ---
    dim3 gav(DD / 128, SS / 128, BB);
    gemm_h<0, true, false><<<gav, gblk, SMEM>>>(
        at, vh, nullptr, rs, nullptr, aoh, SS, DD, SS, SS, 3 * DD,
        (long long)SS * SS, (long long)SS * 3 * DD, (long long)SS * DD, SS);

    // --- x1h = half(LayerNorm(x + aoh)) ---
    ln_mix_kernel<<<MM, blk>>>(x, aoh, gamma, beta, nullptr, x1h);

    // --- h = gelu(x1 @ W1 + b1), half out ---
    dim3 gf1(HH / 128, MM / 128, 1);
    gemm_h<1, true, true><<<gf1, gblk, SMEM>>>(
        x1h, w1T, b1, nullptr, nullptr, hh, MM, HH, DD, DD, DD, 0, 0, 0, 0);

    // --- ff = h @ W2 + b2, fp32 out ---
    dim3 gf2(DD / 128, MM / 128, 1);
    gemm_h<0, false, true><<<gf2, gblk, SMEM>>>(
        hh, w2T, b2, nullptr, nullptr, ff, MM, DD, HH, HH, HH, 0, 0, 0, 0);

    // --- out = LayerNorm(ff + x1h), fp32 ---
    ln_mix_kernel<<<MM, blk>>>(ff, x1h, gamma, beta, out, nullptr);
}

// round 17
// speedup vs baseline: 1.0265x; 1.0082x over previous
#include <cuda_runtime.h>
#include <cuda_fp16.h>
#include <math.h>
#include <stdint.h>

// ---------------------------------------------------------------------------
// B=2, S=4096, D=1024, H=4096, M=B*S=8192
// ---------------------------------------------------------------------------
#define BB   2
#define SS   4096
#define DD   1024
#define HH   4096
#define MM   (BB * SS)

// ---------------------------------------------------------------------------
// Scratch (static device globals; no runtime allocation allowed)
// ---------------------------------------------------------------------------
__device__ __half g_xh   [MM * DD];
__device__ __half g_wqkvT[3 * DD * DD];
__device__ float  g_bqkv [3 * DD];
__device__ __half g_w1T  [(long long)HH * DD];
__device__ __half g_w2T  [(long long)DD * HH];
__device__ __half g_qkv  [(long long)MM * 3 * DD];
__device__ __half g_at   [(long long)BB * SS * SS];   // exp(logits/32), half
__device__ float  g_rs   [MM];                        // rowsum of exp (atomic)
__device__ __half g_aoh  [MM * DD];                   // attn_out, half
__device__ __half g_x1h  [MM * DD];                   // LN1 output, half
__device__ __half g_hh   [(long long)MM * HH];
__device__ __half g_ffh  [MM * DD];                   // FFN2 output, half

// ---------------------------------------------------------------------------
// Side streams + events for fork/join under graph capture.
// Created ONCE at module load (static init): no allocation, no per-call
// guards, deterministic work per kernel_launch call.
// ---------------------------------------------------------------------------
static cudaStream_t s_side1 = nullptr, s_side2 = nullptr;
static cudaEvent_t  s_ev0 = nullptr, s_ev1 = nullptr, s_ev2 = nullptr;
static struct StreamInit {
    StreamInit() {
        cudaStreamCreateWithFlags(&s_side1, cudaStreamNonBlocking);
        cudaStreamCreateWithFlags(&s_side2, cudaStreamNonBlocking);
        cudaEventCreateWithFlags(&s_ev0, cudaEventDisableTiming);
        cudaEventCreateWithFlags(&s_ev1, cudaEventDisableTiming);
        cudaEventCreateWithFlags(&s_ev2, cudaEventDisableTiming);
    }
} s_streamInit;

// ---------------------------------------------------------------------------
// PTX helpers
// ---------------------------------------------------------------------------
__device__ __forceinline__ void mma_f16(float* c, const uint32_t* a, const uint32_t* b) {
    asm volatile(
        "mma.sync.aligned.m16n8k16.row.col.f32.f16.f16.f32 "
        "{%0,%1,%2,%3}, {%4,%5,%6,%7}, {%8,%9}, {%0,%1,%2,%3};\n"
        : "+f"(c[0]), "+f"(c[1]), "+f"(c[2]), "+f"(c[3])
        : "r"(a[0]), "r"(a[1]), "r"(a[2]), "r"(a[3]),
          "r"(b[0]), "r"(b[1]));
}
__device__ __forceinline__ void ldsm_x4(uint32_t* r, uint32_t saddr) {
    asm volatile(
        "ldmatrix.sync.aligned.m8n8.x4.shared.b16 {%0,%1,%2,%3}, [%4];"
        : "=r"(r[0]), "=r"(r[1]), "=r"(r[2]), "=r"(r[3]) : "r"(saddr));
}
__device__ __forceinline__ void ldsm_x4_t(uint32_t* r, uint32_t saddr) {
    asm volatile(
        "ldmatrix.sync.aligned.m8n8.x4.trans.shared.b16 {%0,%1,%2,%3}, [%4];"
        : "=r"(r[0]), "=r"(r[1]), "=r"(r[2]), "=r"(r[3]) : "r"(saddr));
}
__device__ __forceinline__ void cp_async16(uint32_t saddr, const void* gmem) {
    asm volatile("cp.async.cg.shared.global [%0], [%1], 16;\n" :: "r"(saddr), "l"(gmem));
}
__device__ __forceinline__ void cp_commit() {
    asm volatile("cp.async.commit_group;\n");
}
__device__ __forceinline__ void cp_wait1() {
    asm volatile("cp.async.wait_group 1;\n");
}

// ---------------------------------------------------------------------------
// fp16 tensor-core GEMM: C[M,N] = A[M,K] @ B.   (round-14 structure, verbatim)
// B_NT=true : B given as Bt[N,K] row-major (NT), ldmatrix non-trans.
// B_NT=false: B given as  B[K,N] row-major (NN), ldmatrix.trans.
// Epilogue EPI: 0 = +bias, 1 = +bias,GELU,
//               2 = exp(v/32) + per-row atomic sum into rsum (no bias).
// Optional rscale: per-row DIVISOR (softmax normalization in AV).
// CTA tile 128x128, BK=64, 128 threads = 4 warps of 64x64, 2 CTAs/SM.
// 3-stage cp.async pipeline, ldmatrix.x4, register frag double-buffering.
// M,N multiples of 128; K multiple of 64, K/64 >= 2.
// ---------------------------------------------------------------------------
template <int EPI, bool OUT_HALF, bool B_NT>
__global__ void __launch_bounds__(128, 2)
gemm_h(const __half* __restrict__ A, const __half* __restrict__ Bm,
       const float* __restrict__ bias, const float* __restrict__ rscale,
       float* __restrict__ rsum, void* __restrict__ Cv,
       int M, int N, int K, int lda, int ldb,
       long long sA, long long sB, long long sC, long long sR)
{
    constexpr int BM = 128, BN = 128, BK = 64;
    constexpr int LDH2 = 36;                     // A smem pitch, u32 words
    constexpr int PB   = 68;                     // B smem pitch for NN, u32 words
    constexpr int A_STAGE = BM * LDH2;           // 4608 words
    constexpr int B_STAGE = B_NT ? (BN * LDH2)   // 4608 words (NT)
                                 : (BK * PB);    // 4352 words (NN)
    constexpr int STAGE   = A_STAGE + B_STAGE;

    extern __shared__ uint32_t smem_u[];
    const uint32_t sbase = (uint32_t)__cvta_generic_to_shared(smem_u);

    A  += (long long)blockIdx.z * sA;
    Bm += (long long)blockIdx.z * sB;
    if (rscale) rscale += (long long)blockIdx.z * sR;
    if (EPI == 2 && rsum) rsum += (long long)blockIdx.z * sR;

    const int tid  = threadIdx.x;
    const int lane = tid & 31;
    const int wid  = tid >> 5;            // 0..3
    const int m0   = blockIdx.y * BM;
    const int n0   = blockIdx.x * BN;
    const int wm   = (wid & 1) * 64;      // 2 warps in M
    const int wn   = (wid >> 1) * 64;     // 2 warps in N
    const int lr   = lane >> 2;
    const int lc   = lane & 3;

    float acc[4][8][4];
    #pragma unroll
    for (int i = 0; i < 4; ++i)
        #pragma unroll
        for (int j = 0; j < 8; ++j)
            #pragma unroll
            for (int t = 0; t < 4; ++t)
                acc[i][j][t] = 0.0f;

    // ldmatrix per-lane byte offsets within a stage
    uint32_t a_off[4], b_off[4];
    {
        int arow  = wm + (lane & 15);
        int acol2 = (lane >> 4) * 4;
        #pragma unroll
        for (int mi = 0; mi < 4; ++mi)
            a_off[mi] = (uint32_t)(((arow + mi * 16) * LDH2 + acol2) * 4);

        if (B_NT) {
            int brow  = wn + (lane & 7) + ((lane >> 4) & 1) * 8;
            int bcol2 = ((lane >> 3) & 1) * 4;
            #pragma unroll
            for (int p = 0; p < 4; ++p)
                b_off[p] = (uint32_t)((A_STAGE + (brow + p * 16) * LDH2 + bcol2) * 4);
        } else {
            int mat   = lane >> 3;
            int krow  = (mat & 1) * 8 + (lane & 7);
            #pragma unroll
            for (int p = 0; p < 4; ++p) {
                int ncol = wn + p * 16 + (mat >> 1) * 8;
                b_off[p] = (uint32_t)(A_STAGE * 4 + krow * (PB * 4) + ncol * 2);
            }
        }
    }

    auto load_tile = [&](int t) {
        const uint32_t stg = sbase + (uint32_t)((t % 3) * STAGE * 4);
        const int k0 = t * BK;
        #pragma unroll
        for (int p = 0; p < 8; ++p) {
            int idx = tid + p * 128;
            int row = idx >> 3, ch = idx & 7;
            cp_async16(stg + (uint32_t)((row * LDH2 + ch * 4) * 4),
                       A + (long long)(m0 + row) * lda + k0 + ch * 8);
        }
        if (B_NT) {
            #pragma unroll
            for (int p = 0; p < 8; ++p) {
                int idx = tid + p * 128;
                int row = idx >> 3, ch = idx & 7;
                cp_async16(stg + (uint32_t)((A_STAGE + row * LDH2 + ch * 4) * 4),
                           Bm + (long long)(n0 + row) * ldb + k0 + ch * 8);
            }
        } else {
            #pragma unroll
            for (int p = 0; p < 8; ++p) {
                int idx = tid + p * 128;
                int row = idx >> 4, ch = idx & 15;
                cp_async16(stg + (uint32_t)(A_STAGE * 4 + row * (PB * 4) + ch * 16),
                           Bm + (long long)(k0 + row) * ldb + n0 + ch * 8);
            }
        }
    };

    uint32_t af[2][4][4], bf[2][8][2];
    auto load_frags = [&](uint32_t stg, int ks, int buf) {
        const uint32_t kbA = (uint32_t)(ks * 32);
        const uint32_t kbB = B_NT ? kbA : (uint32_t)(ks * 16 * PB * 4);
        #pragma unroll
        for (int mi = 0; mi < 4; ++mi)
            ldsm_x4(af[buf][mi], stg + a_off[mi] + kbA);
        #pragma unroll
        for (int p = 0; p < 4; ++p) {
            uint32_t r[4];
            if (B_NT) ldsm_x4  (r, stg + b_off[p] + kbB);
            else      ldsm_x4_t(r, stg + b_off[p] + kbB);
            bf[buf][2 * p + 0][0] = r[0];
            bf[buf][2 * p + 0][1] = r[1];
            bf[buf][2 * p + 1][0] = r[2];
            bf[buf][2 * p + 1][1] = r[3];
        }
    };

    const int NIT = K / BK;
    load_tile(0); cp_commit();
    load_tile(1); cp_commit();

    for (int it = 0; it < NIT; ++it) {
        cp_wait1();                 // stage `it` resident
        __syncthreads();            // all warps done reading stage (it+2)%3
        if (it + 2 < NIT) load_tile(it + 2);
        cp_commit();                // exactly one group per iteration

        const uint32_t stg = sbase + (uint32_t)((it % 3) * STAGE * 4);
        load_frags(stg, 0, 0);
        #pragma unroll
        for (int ks = 0; ks < 4; ++ks) {
            const int cur = ks & 1;
            if (ks < 3) load_frags(stg, ks + 1, cur ^ 1);
            #pragma unroll
            for (int mi = 0; mi < 4; ++mi)
                #pragma unroll
                for (int nj = 0; nj < 8; ++nj)
                    mma_f16(acc[mi][nj], af[cur][mi], bf[cur][nj]);
        }
    }

    // ---- epilogue ----
    float*  Cf = (float*) Cv + (long long)blockIdx.z * sC;
    __half* Ch = (__half*)Cv + (long long)blockIdx.z * sC;

    float rinv[4][2];
    if (rscale) {
        #pragma unroll
        for (int mi = 0; mi < 4; ++mi)
            #pragma unroll
            for (int hf = 0; hf < 2; ++hf)
                rinv[mi][hf] = 1.0f / rscale[m0 + wm + mi * 16 + lr + hf * 8];
    }

    float rowacc[4][2];
    if (EPI == 2) {
        #pragma unroll
        for (int mi = 0; mi < 4; ++mi) { rowacc[mi][0] = 0.0f; rowacc[mi][1] = 0.0f; }
    }

    #pragma unroll
    for (int mi = 0; mi < 4; ++mi) {
        #pragma unroll
        for (int nj = 0; nj < 8; ++nj) {
            const int col = n0 + wn + nj * 8 + lc * 2;
            float b0 = 0.0f, b1 = 0.0f;
            if (EPI != 2 && bias) { b0 = bias[col]; b1 = bias[col + 1]; }
            #pragma unroll
            for (int hf = 0; hf < 2; ++hf) {
                const int row = m0 + wm + mi * 16 + lr + hf * 8;
                float v0 = acc[mi][nj][hf * 2 + 0] + b0;
                float v1 = acc[mi][nj][hf * 2 + 1] + b1;
                if (EPI == 1) {
                    v0 = 0.5f * v0 * (1.0f + erff(v0 * 0.70710678118654752f));
                    v1 = 0.5f * v1 * (1.0f + erff(v1 * 0.70710678118654752f));
                } else if (EPI == 2) {
                    v0 = __expf(v0 * 0.03125f);
                    v1 = __expf(v1 * 0.03125f);
                    rowacc[mi][hf] += v0 + v1;
                }
                if (rscale) { v0 *= rinv[mi][hf]; v1 *= rinv[mi][hf]; }
                if (OUT_HALF) {
                    *(__half2*)(Ch + (long long)row * N + col) = __floats2half2_rn(v0, v1);
                } else {
                    *(float2*)(Cf + (long long)row * N + col) = make_float2(v0, v1);
                }
            }
        }
    }

    if (EPI == 2) {
        #pragma unroll
        for (int mi = 0; mi < 4; ++mi) {
            #pragma unroll
            for (int hf = 0; hf < 2; ++hf) {
                float s = rowacc[mi][hf];
                s += __shfl_xor_sync(0xffffffffu, s, 1);
                s += __shfl_xor_sync(0xffffffffu, s, 2);
                if (lc == 0)
                    atomicAdd(&rsum[m0 + wm + mi * 16 + lr + hf * 8], s);
            }
        }
    }
}

// ---------------------------------------------------------------------------
// Elementwise fp32 -> half
// ---------------------------------------------------------------------------
__global__ void __launch_bounds__(256)
f2h_kernel(const float4* __restrict__ in, __half2* __restrict__ out, long long n4)
{
    long long i = (long long)blockIdx.x * blockDim.x + threadIdx.x;
    long long stride = (long long)gridDim.x * blockDim.x;
    for (; i < n4; i += stride) {
        float4 v = in[i];
        out[2 * i + 0] = __floats2half2_rn(v.x, v.y);
        out[2 * i + 1] = __floats2half2_rn(v.z, v.w);
    }
}

// ---------------------------------------------------------------------------
// Batched transpose fp32 [D][D] -> half [D][D]^T for 3 weight matrices (z sel)
// ---------------------------------------------------------------------------
__global__ void __launch_bounds__(256)
transpose_f2h3(const float* __restrict__ w0, const float* __restrict__ w1,
               const float* __restrict__ w2, __half* __restrict__ out)
{
    __shared__ float t[32][33];
    const float* in = (blockIdx.z == 0) ? w0 : (blockIdx.z == 1) ? w1 : w2;
    __half* o = out + (long long)blockIdx.z * DD * DD;
    int x = blockIdx.x * 32 + threadIdx.x;
    int y = blockIdx.y * 32 + threadIdx.y;
    #pragma unroll
    for (int i = 0; i < 32; i += 8)
        t[threadIdx.y + i][threadIdx.x] = in[(long long)(y + i) * DD + x];
    __syncthreads();
    x = blockIdx.y * 32 + threadIdx.x;
    y = blockIdx.x * 32 + threadIdx.y;
    #pragma unroll
    for (int i = 0; i < 32; i += 8)
        o[(long long)(y + i) * DD + x] = __float2half_rn(t[threadIdx.x][threadIdx.y + i]);
}

// ---------------------------------------------------------------------------
// Transpose fp32 [R][C] -> half [C][R]
// ---------------------------------------------------------------------------
__global__ void __launch_bounds__(256)
transpose_f2h(const float* __restrict__ in, __half* __restrict__ out, int R, int C)
{
    __shared__ float t[32][33];
    int x = blockIdx.x * 32 + threadIdx.x;
    int y = blockIdx.y * 32 + threadIdx.y;
    #pragma unroll
    for (int i = 0; i < 32; i += 8)
        t[threadIdx.y + i][threadIdx.x] = in[(long long)(y + i) * C + x];
    __syncthreads();
    x = blockIdx.y * 32 + threadIdx.x;
    y = blockIdx.x * 32 + threadIdx.y;
    #pragma unroll
    for (int i = 0; i < 32; i += 8)
        out[(long long)(y + i) * R + x] = __float2half_rn(t[threadIdx.x][threadIdx.y + i]);
}

// ---------------------------------------------------------------------------
// Block reduction helper (sum or max), 256 threads
// ---------------------------------------------------------------------------
__device__ __forceinline__ float block_reduce(float v, bool do_max) {
    __shared__ float sh[33];
    #pragma unroll
    for (int o = 16; o > 0; o >>= 1) {
        float t = __shfl_xor_sync(0xffffffffu, v, o);
        v = do_max ? fmaxf(v, t) : (v + t);
    }
    const int lane = threadIdx.x & 31;
    const int wid  = threadIdx.x >> 5;
    if (lane == 0) sh[wid] = v;
    __syncthreads();
    if (wid == 0) {
        int nw = blockDim.x >> 5;
        v = (lane < nw) ? sh[lane] : (do_max ? -INFINITY : 0.0f);
        #pragma unroll
        for (int o = 16; o > 0; o >>= 1) {
            float t = __shfl_xor_sync(0xffffffffu, v, o);
            v = do_max ? fmaxf(v, t) : (v + t);
        }
        if (lane == 0) sh[32] = v;
    }
    __syncthreads();
    float r = sh[32];
    __syncthreads();
    return r;
}

// ---------------------------------------------------------------------------
// LayerNorm, mixed fp32 + half inputs: v = Xf + Xh  (Xf fp32, Xh half).
// Outputs: Of (fp32, optional), Oh (half, optional).
// ---------------------------------------------------------------------------
__global__ void __launch_bounds__(256)
ln_mix_kernel(const float* __restrict__ Xf, const __half* __restrict__ Xh,
              const float* __restrict__ gamma, const float* __restrict__ beta,
              float* __restrict__ Of, __half* __restrict__ Oh)
{
    constexpr int D = DD;
    const long long base = (long long)blockIdx.x * D;
    const int d = threadIdx.x * 4;

    float4 v = *(const float4*)(Xf + base + d);
    {
        float2 f0 = __half22float2(*(const __half2*)(Xh + base + d));
        float2 f1 = __half22float2(*(const __half2*)(Xh + base + d + 2));
        v.x += f0.x; v.y += f0.y; v.z += f1.x; v.w += f1.y;
    }

    float mean = block_reduce(v.x + v.y + v.z + v.w, false) * (1.0f / D);
    float4 dv = make_float4(v.x - mean, v.y - mean, v.z - mean, v.w - mean);
    float var = block_reduce(dv.x * dv.x + dv.y * dv.y + dv.z * dv.z + dv.w * dv.w,
                             false) * (1.0f / D);
    float inv = rsqrtf(var + 1e-5f);

    float4 gv = *(const float4*)(gamma + d);
    float4 bv = *(const float4*)(beta + d);
    float4 o;
    o.x = dv.x * inv * gv.x + bv.x;
    o.y = dv.y * inv * gv.y + bv.y;
    o.z = dv.z * inv * gv.z + bv.z;
    o.w = dv.w * inv * gv.w + bv.w;
    if (Of) *(float4*)(Of + base + d) = o;
    if (Oh) {
        *(__half2*)(Oh + base + d)     = __floats2half2_rn(o.x, o.y);
        *(__half2*)(Oh + base + d + 2) = __floats2half2_rn(o.z, o.w);
    }
}

// ---------------------------------------------------------------------------
// LayerNorm, two half inputs: v = Xh1 + Xh2; fp32 output.
// ---------------------------------------------------------------------------
__global__ void __launch_bounds__(256)
ln_hh_kernel(const __half* __restrict__ Xh1, const __half* __restrict__ Xh2,
             const float* __restrict__ gamma, const float* __restrict__ beta,
             float* __restrict__ Of)
{
    constexpr int D = DD;
    const long long base = (long long)blockIdx.x * D;
    const int d = threadIdx.x * 4;

    float2 a0 = __half22float2(*(const __half2*)(Xh1 + base + d));
    float2 a1 = __half22float2(*(const __half2*)(Xh1 + base + d + 2));
    float2 b0 = __half22float2(*(const __half2*)(Xh2 + base + d));
    float2 b1 = __half22float2(*(const __half2*)(Xh2 + base + d + 2));
    float4 v = make_float4(a0.x + b0.x, a0.y + b0.y, a1.x + b1.x, a1.y + b1.y);

    float mean = block_reduce(v.x + v.y + v.z + v.w, false) * (1.0f / D);
    float4 dv = make_float4(v.x - mean, v.y - mean, v.z - mean, v.w - mean);
    float var = block_reduce(dv.x * dv.x + dv.y * dv.y + dv.z * dv.z + dv.w * dv.w,
                             false) * (1.0f / D);
    float inv = rsqrtf(var + 1e-5f);

    float4 gv = *(const float4*)(gamma + d);
    float4 bv = *(const float4*)(beta + d);
    float4 o;
    o.x = dv.x * inv * gv.x + bv.x;
    o.y = dv.y * inv * gv.y + bv.y;
    o.z = dv.z * inv * gv.z + bv.z;
    o.w = dv.w * inv * gv.w + bv.w;
    *(float4*)(Of + base + d) = o;
}

// ---------------------------------------------------------------------------
// kernel_launch
// Inputs: input_embedding, Wq, bq, Wk, bk, Wv, bv, W1, b1, W2, b2, gamma, beta
// Fork/join: side1 = W1/W2 transposes (join before FFN1), side2 = x->half
// (join before QKV). Both forked off the capture stream via events.
// ---------------------------------------------------------------------------
extern "C" void kernel_launch(void* const* d_in, const int* /*in_sizes*/, int /*n_in*/,
                              void* d_out, int /*out_size*/)
{
    const float* x     = (const float*)d_in[0];
    const float* Wq    = (const float*)d_in[1];
    const float* bq    = (const float*)d_in[2];
    const float* Wk    = (const float*)d_in[3];
    const float* bk    = (const float*)d_in[4];
    const float* Wv    = (const float*)d_in[5];
    const float* bv    = (const float*)d_in[6];
    const float* W1    = (const float*)d_in[7];
    const float* b1    = (const float*)d_in[8];
    const float* W2    = (const float*)d_in[9];
    const float* b2    = (const float*)d_in[10];
    const float* gamma = (const float*)d_in[11];
    const float* beta  = (const float*)d_in[12];
    float* out = (float*)d_out;

    __half *xh, *wqkvT, *w1T, *w2T, *qkv, *at, *aoh, *x1h, *hh, *ffh;
    float *bqkv, *rs;
    cudaGetSymbolAddress((void**)&xh,    g_xh);
    cudaGetSymbolAddress((void**)&wqkvT, g_wqkvT);
    cudaGetSymbolAddress((void**)&bqkv,  g_bqkv);
    cudaGetSymbolAddress((void**)&w1T,   g_w1T);
    cudaGetSymbolAddress((void**)&w2T,   g_w2T);
    cudaGetSymbolAddress((void**)&qkv,   g_qkv);
    cudaGetSymbolAddress((void**)&at,    g_at);
    cudaGetSymbolAddress((void**)&rs,    g_rs);
    cudaGetSymbolAddress((void**)&aoh,   g_aoh);
    cudaGetSymbolAddress((void**)&x1h,   g_x1h);
    cudaGetSymbolAddress((void**)&hh,    g_hh);
    cudaGetSymbolAddress((void**)&ffh,   g_ffh);

    const int SMEM = 3 * 9216 * 4;   // 110592 B per CTA (2 CTAs/SM)
    cudaFuncSetAttribute((const void*)gemm_h<0, true,  true>,
                         cudaFuncAttributeMaxDynamicSharedMemorySize, SMEM);
    cudaFuncSetAttribute((const void*)gemm_h<2, true,  true>,
                         cudaFuncAttributeMaxDynamicSharedMemorySize, SMEM);
    cudaFuncSetAttribute((const void*)gemm_h<0, true,  false>,
                         cudaFuncAttributeMaxDynamicSharedMemorySize, SMEM);
    cudaFuncSetAttribute((const void*)gemm_h<1, true,  true>,
                         cudaFuncAttributeMaxDynamicSharedMemorySize, SMEM);

    dim3 gblk(128);          // gemm CTAs: 4 warps
    dim3 blk(256);
    dim3 tblk(32, 8);

    // --- fork: side streams branch off the capture stream ---
    cudaEventRecord(s_ev0, 0);
    cudaStreamWaitEvent(s_side1, s_ev0, 0);
    cudaStreamWaitEvent(s_side2, s_ev0, 0);

    // side1: FFN weight transposes (needed only at FFN1/FFN2)
    transpose_f2h<<<dim3(HH/32, DD/32), tblk, 0, s_side1>>>(W1, w1T, DD, HH);
    transpose_f2h<<<dim3(DD/32, HH/32), tblk, 0, s_side1>>>(W2, w2T, HH, DD);
    cudaEventRecord(s_ev1, s_side1);

    // side2: input fp32 -> half (needed at QKV)
    f2h_kernel<<<1184, blk, 0, s_side2>>>(
        (const float4*)x, (__half2*)xh, (long long)MM * DD / 4);
    cudaEventRecord(s_ev2, s_side2);

    // main: QKV weight transpose + bias concat + rowsum zero
    transpose_f2h3<<<dim3(DD/32, DD/32, 3), tblk>>>(Wq, Wk, Wv, wqkvT);
    cudaMemsetAsync(rs, 0, MM * sizeof(float));
    cudaMemcpyAsync(bqkv,          bq, DD * sizeof(float), cudaMemcpyDeviceToDevice);
    cudaMemcpyAsync(bqkv + DD,     bk, DD * sizeof(float), cudaMemcpyDeviceToDevice);
    cudaMemcpyAsync(bqkv + 2 * DD, bv, DD * sizeof(float), cudaMemcpyDeviceToDevice);

    // join: xh ready before QKV
    cudaStreamWaitEvent(0, s_ev2, 0);

    // --- fused QKV projection ---
    dim3 gqkv(3 * DD / 128, MM / 128, 1);
    gemm_h<0, true, true><<<gqkv, gblk, SMEM>>>(
        xh, wqkvT, bqkv, nullptr, nullptr, qkv,
        MM, 3 * DD, DD, DD, DD, 0, 0, 0, 0);

    const __half* qh = qkv;
    const __half* kh = qkv + DD;
    const __half* vh = qkv + 2 * DD;

    // --- at[b] = exp(k[b] @ q[b]^T / 32), rowsums via atomics ---
    dim3 gsc(SS / 128, SS / 128, BB);
    gemm_h<2, true, true><<<gsc, gblk, SMEM>>>(
        kh, qh, nullptr, nullptr, rs, at, SS, SS, DD, 3 * DD, 3 * DD,
        (long long)SS * 3 * DD, (long long)SS * 3 * DD, (long long)SS * SS, SS);

    // --- aoh[b] = (at[b] @ v[b]) / rs  (NN path, half out) ---
    dim3 gav(DD / 128, SS / 128, BB);
    gemm_h<0, true, false><<<gav, gblk, SMEM>>>(
        at, vh, nullptr, rs, nullptr, aoh, SS, DD, SS, SS, 3 * DD,
        (long long)SS * SS, (long long)SS * 3 * DD, (long long)SS * DD, SS);

    // --- x1h = half(LayerNorm(x + aoh)) ---
    ln_mix_kernel<<<MM, blk>>>(x, aoh, gamma, beta, nullptr, x1h);

    // join: w1T/w2T ready before FFN1
    cudaStreamWaitEvent(0, s_ev1, 0);

    // --- h = gelu(x1 @ W1 + b1), half out ---
    dim3 gf1(HH / 128, MM / 128, 1);
    gemm_h<1, true, true><<<gf1, gblk, SMEM>>>(
        x1h, w1T, b1, nullptr, nullptr, hh, MM, HH, DD, DD, DD, 0, 0, 0, 0);

    // --- ffh = h @ W2 + b2, half out ---
    dim3 gf2(DD / 128, MM / 128, 1);
    gemm_h<0, true, true><<<gf2, gblk, SMEM>>>(
        hh, w2T, b2, nullptr, nullptr, ffh, MM, DD, HH, HH, HH, 0, 0, 0, 0);

    // --- out = LayerNorm(ffh + x1h), fp32 ---
    ln_hh_kernel<<<MM, blk>>>(ffh, x1h, gamma, beta, out);
}